// round 15
// baseline (speedup 1.0000x reference)
#include <cuda_runtime.h>
#include <cuda_fp16.h>
#include <cstdint>

// ---------------- problem constants ----------------
#define T_SZ   3500
#define L_SZ   256
#define M_SZ   1024
#define NROWS  56000
#define ROWS_CTA 64
#define NCTA   (NROWS / ROWS_CTA)     // 875 exactly (2.96 waves @ 2 CTA/SM)
#define NTHREADS 256

// ---------------- SMEM layout (bytes, dynamic) ----------------
#define SM_A   0          // 64 rows x 256 fp16, rowstride 512B, swizzled = 32KB
#define SM_B   32768      // per-warp: wid*8KB; 2 bufs x 4KB (2 halves x 2KB) = 64KB
#define SM_B2  98304      // 1024 floats (4KB)
#define SM_A2  102400     // 64 floats (256B)
#define SM_RS  102656     // 64 floats (256B)
#define SMEM_TOTAL 102912 // x2 CTAs = 205,824 <= 228KB

// ---------------- device globals (allocation-free scratch) ----------------
__device__ __half g_ct[M_SZ * L_SZ];  // centroids, fp16-rounded, [n][k]
__device__ float g_b2[M_SZ];          // |c|^2 of the ROUNDED centroids

// ---------------- PTX helpers ----------------
__device__ __forceinline__ uint32_t smem_to_u32(const void* p) {
    uint32_t a;
    asm("{ .reg .u64 t; cvta.to.shared.u64 t, %1; cvt.u32.u64 %0, t; }"
        : "=r"(a) : "l"(p));
    return a;
}

__device__ __forceinline__ void ldsm4(uint32_t* r, uint32_t addr) {
    asm volatile("ldmatrix.sync.aligned.m8n8.x4.shared.b16 {%0,%1,%2,%3}, [%4];"
        : "=r"(r[0]), "=r"(r[1]), "=r"(r[2]), "=r"(r[3]) : "r"(addr));
}

__device__ __forceinline__ void mma16816(float* d, const uint32_t* a, const uint32_t* b) {
    asm volatile(
        "mma.sync.aligned.m16n8k16.row.col.f32.f16.f16.f32 "
        "{%0,%1,%2,%3}, {%4,%5,%6,%7}, {%8,%9}, {%0,%1,%2,%3};"
        : "+f"(d[0]), "+f"(d[1]), "+f"(d[2]), "+f"(d[3])
        : "r"(a[0]), "r"(a[1]), "r"(a[2]), "r"(a[3]), "r"(b[0]), "r"(b[1]));
}

// q = x^-5.5 = rsqrt(x^11); x in [1, ~120] so x^11 <= ~1e23 fits fp32.
__device__ __forceinline__ float pow_m55(float x) {
    float x2 = x * x;
    float x4 = x2 * x2;
    float x8 = x4 * x4;
    return rsqrtf(x8 * x2 * x);
}

#define CP_ASYNC16(dst, src) \
    asm volatile("cp.async.cg.shared.global [%0], [%1], 16;" :: "r"(dst), "l"(src))
#define CP_COMMIT asm volatile("cp.async.commit_group;" ::: "memory")
#define CP_WAIT1  asm volatile("cp.async.wait_group 1;" ::: "memory")

// ---------------------------------------------------------------------------
// Kernel 1 (prep): centroids -> fp16 + b2 of rounded values (1 warp per row)
// ---------------------------------------------------------------------------
__global__ void som_prep_kernel(const float* __restrict__ cent) {
    int m = blockIdx.x * 8 + (threadIdx.x >> 5);
    int lane = threadIdx.x & 31;
    const float4* c4 = reinterpret_cast<const float4*>(cent + (size_t)m * L_SZ);
    float s = 0.f;
#pragma unroll
    for (int i = 0; i < 2; ++i) {
        float4 v = c4[lane * 2 + i];
        float vv[4] = {v.x, v.y, v.z, v.w};
        uint32_t pk[2];
#pragma unroll
        for (int j = 0; j < 2; ++j) {
            __half h0 = __float2half_rn(vv[2*j]);
            __half h1 = __float2half_rn(vv[2*j+1]);
            float r0 = __half2float(h0), r1 = __half2float(h1);
            s += r0 * r0 + r1 * r1;
            pk[j] = ((uint32_t)__half_as_ushort(h1) << 16) | __half_as_ushort(h0);
        }
        reinterpret_cast<uint2*>(g_ct + (size_t)m * L_SZ)[lane * 2 + i] =
            make_uint2(pk[0], pk[1]);
    }
#pragma unroll
    for (int o = 16; o > 0; o >>= 1) s += __shfl_down_sync(0xffffffffu, s, o);
    if (lane == 0) g_b2[m] = s;
}

// ---------------------------------------------------------------------------
// Kernel 2 (main): fp16 GEMM (m16n8k16). PER-WARP self-paced cp.async
// pipelines (no CTA/pair barriers in the loop). NC-PAIR BLOCKING: each pass
// computes 2 x 128-col chunks with shared A fragments (12 LDSM per 32 MMA).
// B chunks 32-k x 2 halves (4KB), 2-deep, 32 steps. Deferred row-sum
// reduction + fused normalization. CTA = 64 rows x 1024 cols, 8 warps (2x4),
// warp tile 32 x (2x32). 2 CTAs/SM.
// ---------------------------------------------------------------------------
__global__ void __launch_bounds__(NTHREADS, 2)
som_mma_kernel(const float* __restrict__ z,
               const float* __restrict__ tw,
               float* __restrict__ out)
{
    extern __shared__ char smem[];
    const uint32_t sb = smem_to_u32(smem);
    const int tid  = threadIdx.x;
    const int wid  = tid >> 5;
    const int l    = tid & 31;
    const int wr   = wid >> 2;        // 0..1 (32 rows each)
    const int wc   = wid & 3;         // 0..3 (32 cols within each 128-chunk)
    const int row0 = blockIdx.x * ROWS_CTA;

    float* b2s = (float*)(smem + SM_B2);
    float* a2s = (float*)(smem + SM_A2);
    float* rss = (float*)(smem + SM_RS);

    for (int i = tid; i < M_SZ; i += NTHREADS) b2s[i] = g_b2[i];
    if (tid < ROWS_CTA) rss[tid] = 0.f;

    // ---- per-warp B loader: step s = pass*8 + kcb ----
    // buffer 4KB = 2 halves (h = col chunk within pass) x (32 n x 32 k fp16),
    // half layout: n*64 + ((k8 ^ ((n>>1)&3))<<4)   [R11-verified swizzle]
    // lane: k8 = l&3 (16B chunk in 64B row), nsub = l>>2; n = i*8 + nsub.
    const uint32_t bwbase = sb + SM_B + (uint32_t)wid * 8192u;
    const int k8 = l & 3, nsub = l >> 2;
    const __half* bsrc0 = g_ct + ((size_t)(wc * 32 + nsub) * 256 + k8 * 8);
    const uint32_t dln = (uint32_t)(nsub * 64) + ((uint32_t)(k8 ^ ((nsub >> 1) & 3)) << 4);
    auto load_step = [&](int s) {
        const uint32_t buf = bwbase + (uint32_t)(s & 1) * 4096u;
        const int pass = s >> 3, kcb = s & 7;
        const __half* src0 = bsrc0 + (size_t)pass * 65536 + kcb * 32;
#pragma unroll
        for (int h = 0; h < 2; ++h) {
            const __half* srch = src0 + h * 32768;      // +128 cols
            const uint32_t bufh = buf + (uint32_t)h * 2048u;
#pragma unroll
            for (int i = 0; i < 4; ++i) {
                // n = i*8 + nsub; row stride in gmem = 256 fp16
                const uint32_t dst = bufh + dln + (uint32_t)i * 512u
                    + ((uint32_t)((((i * 8) >> 1) & 3) & ~((nsub >> 1) & 0)) << 0); // placeholder no-op
                // recompute exactly (i*8+nsub):
                (void)dst;
                const int n = i * 8 + nsub;
                const uint32_t d2 = bufh + (uint32_t)(n * 64)
                    + ((uint32_t)(k8 ^ ((n >> 1) & 3)) << 4);
                CP_ASYNC16(d2, srch + (size_t)(i * 8) * 256);
            }
        }
    };

    load_step(0);
    CP_COMMIT;
    load_step(1);
    CP_COMMIT;

    // ---- A prologue: wz = z*tw -> fp16, swizzled smem; a2 from ROUNDED ----
    {
        const int r = tid >> 2;            // row 0..63
        const int seg = tid & 3;           // 64-k quarter
        const int grow = row0 + r;
        const float twv = tw[grow % T_SZ];
        float s = 0.f;
        const float4* zr = reinterpret_cast<const float4*>(z + (size_t)grow * L_SZ) + seg * 16;
#pragma unroll
        for (int p = 0; p < 8; ++p) {
            float4 v0 = zr[p * 2], v1 = zr[p * 2 + 1];
            float w[8] = {v0.x*twv, v0.y*twv, v0.z*twv, v0.w*twv,
                          v1.x*twv, v1.y*twv, v1.z*twv, v1.w*twv};
            uint32_t pk[4];
#pragma unroll
            for (int j = 0; j < 4; ++j) {
                __half h0 = __float2half_rn(w[2*j]);
                __half h1 = __float2half_rn(w[2*j+1]);
                float r0 = __half2float(h0), r1 = __half2float(h1);
                s += r0 * r0 + r1 * r1;
                pk[j] = ((uint32_t)__half_as_ushort(h1) << 16) | __half_as_ushort(h0);
            }
            const int kc = seg * 8 + p;                         // 16B chunk 0..31
            *(uint4*)(smem + SM_A + r * 512 + ((kc ^ (r & 7)) << 4)) =
                make_uint4(pk[0], pk[1], pk[2], pk[3]);
        }
        s += __shfl_xor_sync(0xffffffffu, s, 1);
        s += __shfl_xor_sync(0xffffffffu, s, 2);
        if (seg == 0) a2s[r] = s;
    }
    __syncthreads();   // A + a2 + b2 visible; last CTA-wide sync until norm.

    // ---- lane-constant address pieces ----
    const int swz = l & 7;
    uint32_t aRow[2];
#pragma unroll
    for (int mf = 0; mf < 2; ++mf)
        aRow[mf] = (uint32_t)(wr * 32 + mf * 16 + (l & 15)) * 512;
    const int aKpart = l >> 4;                     // +1 chunk for lanes 16-31
    uint32_t bOff[2];
    int bSw[2];
#pragma unroll
    for (int np = 0; np < 2; ++np) {
        const int bIdx = np * 16 + (l & 7) + ((l & 16) >> 1);   // local n 0..31
        bOff[np] = (uint32_t)bIdx * 64;
        bSw[np] = (bIdx >> 1) & 3;
    }
    const int bKpart = (l >> 3) & 1;

    float acc[2][2][4][4];                         // [h][mf][nf][e]
#pragma unroll
    for (int h = 0; h < 2; ++h)
#pragma unroll
        for (int mf = 0; mf < 2; ++mf)
#pragma unroll
            for (int nf = 0; nf < 4; ++nf)
#pragma unroll
                for (int e = 0; e < 4; ++e) acc[h][mf][nf][e] = 0.f;

    float rsumr[2][2] = {{0.f, 0.f}, {0.f, 0.f}};   // deferred row sums

    const uint32_t aB = sb + SM_A;

    for (int pass = 0; pass < 4; ++pass) {
        for (int kcb = 0; kcb < 8; ++kcb) {
            const int s = pass * 8 + kcb;

            // per-warp: wait for step s data (s+1 in flight); warp-local sync
            CP_WAIT1;
            __syncwarp();

            const uint32_t buf = bwbase + (uint32_t)(s & 1) * 4096u;

            // fragments for both k16s of this 32-k step; A shared across h
            uint32_t af[2][2][4];      // [k16][mf]
            uint32_t bf[2][2][2][4];   // [k16][h][np]
#pragma unroll
            for (int k16 = 0; k16 < 2; ++k16) {
                const int kcA = kcb * 4 + k16 * 2 + aKpart;    // A chunk 0..31
                const int kcB = k16 * 2 + bKpart;              // B chunk 0..3
#pragma unroll
                for (int mf = 0; mf < 2; ++mf)
                    ldsm4(af[k16][mf], aB + aRow[mf] + ((kcA ^ swz) << 4));
#pragma unroll
                for (int h = 0; h < 2; ++h)
#pragma unroll
                    for (int np = 0; np < 2; ++np)
                        ldsm4(bf[k16][h][np],
                              buf + (uint32_t)h * 2048u + bOff[np] + ((kcB ^ bSw[np]) << 4));
            }

            // prefetch s+2 (same parity buffer; reads above already issued)
            if (s + 2 < 32) { load_step(s + 2); }
            CP_COMMIT;

#pragma unroll
            for (int k16 = 0; k16 < 2; ++k16)
#pragma unroll
                for (int h = 0; h < 2; ++h)
#pragma unroll
                    for (int mf = 0; mf < 2; ++mf)
#pragma unroll
                        for (int nf = 0; nf < 4; ++nf)
                            mma16816(acc[h][mf][nf], af[k16][mf],
                                     &bf[k16][h][nf >> 1][(nf & 1) * 2]);
        }

        // ---- epilogue over the pass's 256 cols (warp-local) ----
#pragma unroll
        for (int h = 0; h < 2; ++h)
#pragma unroll
            for (int mf = 0; mf < 2; ++mf)
#pragma unroll
                for (int rh = 0; rh < 2; ++rh) {
                    const int row = wr * 32 + mf * 16 + rh * 8 + (l >> 2);
                    const float a2v = a2s[row];
                    float rsum = 0.f;
                    float2 st[4];
#pragma unroll
                    for (int nf = 0; nf < 4; ++nf) {
                        const int mcol = pass * 256 + h * 128 + wc * 32 + nf * 8 + (l & 3) * 2;
                        float d0 = a2v + b2s[mcol]     - 2.f * acc[h][mf][nf][rh * 2];
                        float d1 = a2v + b2s[mcol + 1] - 2.f * acc[h][mf][nf][rh * 2 + 1];
                        d0 = fmaxf(d0, 0.f); d1 = fmaxf(d1, 0.f);
                        float q0 = pow_m55(fmaf(d0, 0.1f, 1.f));
                        float q1 = pow_m55(fmaf(d1, 0.1f, 1.f));
                        rsum += q0 + q1;
                        st[nf] = make_float2(q0, q1);
                        acc[h][mf][nf][rh * 2] = 0.f;
                        acc[h][mf][nf][rh * 2 + 1] = 0.f;
                    }
                    rsumr[mf][rh] += rsum;
                    float* orow = out + (size_t)(row0 + row) * M_SZ
                                  + pass * 256 + h * 128 + wc * 32;
#pragma unroll
                    for (int nf = 0; nf < 4; ++nf)
                        *(float2*)(orow + nf * 8 + (l & 3) * 2) = st[nf];
                }
    }

    // ---- deferred row-sum reduction (once per kernel) ----
#pragma unroll
    for (int mf = 0; mf < 2; ++mf)
#pragma unroll
        for (int rh = 0; rh < 2; ++rh) {
            float v = rsumr[mf][rh];
            v += __shfl_xor_sync(0xffffffffu, v, 1);
            v += __shfl_xor_sync(0xffffffffu, v, 2);
            if ((l & 3) == 0) {
                const int row = wr * 32 + mf * 16 + rh * 8 + (l >> 2);
                atomicAdd(&rss[row], v);
            }
        }

    // ---- fused normalization: re-read tile (L2-resident), scale, rewrite ----
    __syncthreads();
    if (tid < ROWS_CTA) rss[tid] = 1.f / (rss[tid] + 1e-8f);
    __syncthreads();
#pragma unroll 4
    for (int i = tid; i < ROWS_CTA * 256; i += NTHREADS) {
        const int r_ = i >> 8;
        const float inv = rss[r_];
        float4* p4 = reinterpret_cast<float4*>(out + (size_t)(row0 + r_) * M_SZ) + (i & 255);
        float4 v = *p4;
        v.x *= inv; v.y *= inv; v.z *= inv; v.w *= inv;
        *p4 = v;
    }
}

// ---------------------------------------------------------------------------
extern "C" void kernel_launch(void* const* d_in, const int* in_sizes, int n_in,
                              void* d_out, int out_size)
{
    const float* z    = (const float*)d_in[0];   // (16, 3500, 256)
    const float* cent = (const float*)d_in[1];   // (1024, 256)
    const float* tw   = (const float*)d_in[2];   // (3500)
    float* out = (float*)d_out;                  // (16, 3500, 1024)

    cudaFuncSetAttribute(som_mma_kernel,
                         cudaFuncAttributeMaxDynamicSharedMemorySize, SMEM_TOTAL);

    som_prep_kernel<<<M_SZ / 8, 256>>>(cent);
    som_mma_kernel<<<NCTA, NTHREADS, SMEM_TOTAL>>>(z, tw, out);
}

// round 16
// speedup vs baseline: 1.2013x; 1.2013x over previous
#include <cuda_runtime.h>
#include <cuda_fp16.h>
#include <cstdint>

// ---------------- problem constants ----------------
#define T_SZ   3500
#define L_SZ   256
#define M_SZ   1024
#define NROWS  56000
#define ROWS_CTA 64
#define NCTA   (NROWS / ROWS_CTA)     // 875 exactly (2.96 waves @ 2 CTA/SM)
#define NTHREADS 256

// ---------------- SMEM layout (bytes, dynamic) ----------------
#define SM_A   0          // 64 rows x 256 fp16, rowstride 512B, swizzled = 32KB
#define SM_B   32768      // 4 slices (per wc) x 3 bufs x 4KB = 48KB
#define SM_B2  81920      // 1024 floats (4KB)
#define SM_A2  86016      // 64 floats (256B)
#define SM_RS  86272      // 64 floats (256B)
#define SMEM_TOTAL 86528  // x2 CTAs = 173,056 <= 228KB

// ---------------- device globals (allocation-free scratch) ----------------
__device__ __half g_ct[M_SZ * L_SZ];  // centroids, fp16-rounded, [n][k]
__device__ float g_b2[M_SZ];          // |c|^2 of the ROUNDED centroids

// ---------------- PTX helpers ----------------
__device__ __forceinline__ uint32_t smem_to_u32(const void* p) {
    uint32_t a;
    asm("{ .reg .u64 t; cvta.to.shared.u64 t, %1; cvt.u32.u64 %0, t; }"
        : "=r"(a) : "l"(p));
    return a;
}

__device__ __forceinline__ void ldsm4(uint32_t* r, uint32_t addr) {
    asm volatile("ldmatrix.sync.aligned.m8n8.x4.shared.b16 {%0,%1,%2,%3}, [%4];"
        : "=r"(r[0]), "=r"(r[1]), "=r"(r[2]), "=r"(r[3]) : "r"(addr));
}

__device__ __forceinline__ void mma16816(float* d, const uint32_t* a, const uint32_t* b) {
    asm volatile(
        "mma.sync.aligned.m16n8k16.row.col.f32.f16.f16.f32 "
        "{%0,%1,%2,%3}, {%4,%5,%6,%7}, {%8,%9}, {%0,%1,%2,%3};"
        : "+f"(d[0]), "+f"(d[1]), "+f"(d[2]), "+f"(d[3])
        : "r"(a[0]), "r"(a[1]), "r"(a[2]), "r"(a[3]), "r"(b[0]), "r"(b[1]));
}

// q = x^-5.5 = rsqrt(x^11); x in [1, ~120] so x^11 <= ~1e23 fits fp32.
__device__ __forceinline__ float pow_m55(float x) {
    float x2 = x * x;
    float x4 = x2 * x2;
    float x8 = x4 * x4;
    return rsqrtf(x8 * x2 * x);
}

#define CP_ASYNC16(dst, src) \
    asm volatile("cp.async.cg.shared.global [%0], [%1], 16;" :: "r"(dst), "l"(src))
#define CP_COMMIT asm volatile("cp.async.commit_group;" ::: "memory")
#define CP_WAIT1  asm volatile("cp.async.wait_group 1;" ::: "memory")
#define PAIR_BAR(id) \
    asm volatile("bar.sync %0, 64;" :: "r"(id) : "memory")

// ---------------------------------------------------------------------------
// Kernel 1 (prep): centroids -> fp16 + b2 of rounded values (1 warp per row)
// ---------------------------------------------------------------------------
__global__ void som_prep_kernel(const float* __restrict__ cent) {
    int m = blockIdx.x * 8 + (threadIdx.x >> 5);
    int lane = threadIdx.x & 31;
    const float4* c4 = reinterpret_cast<const float4*>(cent + (size_t)m * L_SZ);
    float s = 0.f;
#pragma unroll
    for (int i = 0; i < 2; ++i) {
        float4 v = c4[lane * 2 + i];
        float vv[4] = {v.x, v.y, v.z, v.w};
        uint32_t pk[2];
#pragma unroll
        for (int j = 0; j < 2; ++j) {
            __half h0 = __float2half_rn(vv[2*j]);
            __half h1 = __float2half_rn(vv[2*j+1]);
            float r0 = __half2float(h0), r1 = __half2float(h1);
            s += r0 * r0 + r1 * r1;
            pk[j] = ((uint32_t)__half_as_ushort(h1) << 16) | __half_as_ushort(h0);
        }
        reinterpret_cast<uint2*>(g_ct + (size_t)m * L_SZ)[lane * 2 + i] =
            make_uint2(pk[0], pk[1]);
    }
#pragma unroll
    for (int o = 16; o > 0; o >>= 1) s += __shfl_down_sync(0xffffffffu, s, o);
    if (lane == 0) g_b2[m] = s;
}

// ---------------------------------------------------------------------------
// Kernel 2 (main): fp16 GEMM (m16n8k16). B slices PAIR-SHARED (warps
// {wc, wc+4}), leader (wr=0) loads; 3-deep 4KB buffers -> ONE pair barrier
// per step (release barrier eliminated: buf[(s+2)%3]=buf[(s-1)%3], whose
// reads completed before the step-s barrier). Pipelined fragments, deferred
// row-sum reduction, fused normalization. CTA = 64 rows x 1024 cols,
// 8 warps (2x4), warp tile 32x32. 2 CTAs/SM.
// ---------------------------------------------------------------------------
__global__ void __launch_bounds__(NTHREADS, 2)
som_mma_kernel(const float* __restrict__ z,
               const float* __restrict__ tw,
               float* __restrict__ out)
{
    extern __shared__ char smem[];
    const uint32_t sb = smem_to_u32(smem);
    const int tid  = threadIdx.x;
    const int wid  = tid >> 5;
    const int l    = tid & 31;
    const int wr   = wid >> 2;        // 0..1 (32 rows each); wr==0 -> leader
    const int wc   = wid & 3;         // 0..3 (32 cols each within 128-chunk)
    const int row0 = blockIdx.x * ROWS_CTA;
    const bool leader = (wr == 0);

    float* b2s = (float*)(smem + SM_B2);
    float* a2s = (float*)(smem + SM_A2);
    float* rss = (float*)(smem + SM_RS);

    for (int i = tid; i < M_SZ; i += NTHREADS) b2s[i] = g_b2[i];
    if (tid < ROWS_CTA) rss[tid] = 0.f;

    // ---- pair-shared B loader (leader only), R12 layout/addressing ----
    // step s = nc*4 + kcb; 4KB buffer = 32 n x 64 k fp16, rowstride 128B;
    // dst chunk layout: n*128 + ((k8 ^ (n&7))<<4).
    const uint32_t slice = sb + SM_B + (uint32_t)wc * 12288u;
    const int k8 = l & 7, nsub = l >> 3;
    const __half* bsrc0 = g_ct + ((size_t)(wc * 32 + nsub) * 256 + k8 * 8);
    const uint32_t dstA = (uint32_t)(nsub * 128) + ((uint32_t)(k8 ^ nsub) << 4);
    const uint32_t dstB = (uint32_t)(nsub * 128 + 512) + ((uint32_t)(k8 ^ (nsub + 4)) << 4);
    auto load_step = [&](int s) {
        const uint32_t buf = slice + (uint32_t)(s % 3) * 4096u;
        const __half* src = bsrc0 + (s >> 2) * 32768 + (s & 3) * 64;
#pragma unroll
        for (int i = 0; i < 4; ++i) {
            CP_ASYNC16(buf + dstA + (uint32_t)i * 1024u, src + i * 2048);
            CP_ASYNC16(buf + dstB + (uint32_t)i * 1024u, src + i * 2048 + 1024);
        }
    };

    if (leader) {
        load_step(0);
        CP_COMMIT;
        load_step(1);
        CP_COMMIT;
    }

    // ---- A prologue: wz = z*tw -> fp16, swizzled smem; a2 from ROUNDED ----
    {
        const int r = tid >> 2;            // row 0..63
        const int seg = tid & 3;           // 64-k quarter
        const int grow = row0 + r;
        const float twv = tw[grow % T_SZ];
        float s = 0.f;
        const float4* zr = reinterpret_cast<const float4*>(z + (size_t)grow * L_SZ) + seg * 16;
#pragma unroll
        for (int p = 0; p < 8; ++p) {
            float4 v0 = zr[p * 2], v1 = zr[p * 2 + 1];
            float w[8] = {v0.x*twv, v0.y*twv, v0.z*twv, v0.w*twv,
                          v1.x*twv, v1.y*twv, v1.z*twv, v1.w*twv};
            uint32_t pk[4];
#pragma unroll
            for (int j = 0; j < 4; ++j) {
                __half h0 = __float2half_rn(w[2*j]);
                __half h1 = __float2half_rn(w[2*j+1]);
                float r0 = __half2float(h0), r1 = __half2float(h1);
                s += r0 * r0 + r1 * r1;
                pk[j] = ((uint32_t)__half_as_ushort(h1) << 16) | __half_as_ushort(h0);
            }
            const int kc = seg * 8 + p;                         // 16B chunk 0..31
            *(uint4*)(smem + SM_A + r * 512 + ((kc ^ (r & 7)) << 4)) =
                make_uint4(pk[0], pk[1], pk[2], pk[3]);
        }
        s += __shfl_xor_sync(0xffffffffu, s, 1);
        s += __shfl_xor_sync(0xffffffffu, s, 2);
        if (seg == 0) a2s[r] = s;
    }
    __syncthreads();   // A + a2 + b2 visible; last CTA-wide sync until norm.

    // ---- lane-constant address pieces ----
    const int swz = l & 7;
    uint32_t aRow[2];
#pragma unroll
    for (int mf = 0; mf < 2; ++mf)
        aRow[mf] = (uint32_t)(wr * 32 + mf * 16 + (l & 15)) * 512;
    const int aKpart = l >> 4;                     // +1 chunk for lanes 16-31
    uint32_t bOff[2];
    int bSw[2];
#pragma unroll
    for (int np = 0; np < 2; ++np) {
        const int bIdx = np * 16 + (l & 7) + ((l & 16) >> 1);   // local n 0..31
        bOff[np] = (uint32_t)bIdx * 128;
        bSw[np] = bIdx & 7;
    }
    const int bKpart = (l >> 3) & 1;

    float acc[2][4][4];
#pragma unroll
    for (int mf = 0; mf < 2; ++mf)
#pragma unroll
        for (int nf = 0; nf < 4; ++nf)
#pragma unroll
            for (int e = 0; e < 4; ++e) acc[mf][nf][e] = 0.f;

    float rsumr[2][2] = {{0.f, 0.f}, {0.f, 0.f}};   // deferred row sums

    const uint32_t aB = sb + SM_A;
    auto ld_frags = [&](uint32_t buf, int kcb, int k16,
                        uint32_t af[2][4], uint32_t bf[2][4]) {
        const int kcA = kcb * 8 + k16 * 2 + aKpart;
        const int kcB = k16 * 2 + bKpart;
#pragma unroll
        for (int mf = 0; mf < 2; ++mf)
            ldsm4(af[mf], aB + aRow[mf] + ((kcA ^ swz) << 4));
#pragma unroll
        for (int np = 0; np < 2; ++np)
            ldsm4(bf[np], buf + bOff[np] + ((kcB ^ bSw[np]) << 4));
    };
    auto do_mmas = [&](uint32_t af[2][4], uint32_t bf[2][4]) {
#pragma unroll
        for (int mf = 0; mf < 2; ++mf)
#pragma unroll
            for (int nf = 0; nf < 4; ++nf)
                mma16816(acc[mf][nf], af[mf], &bf[nf >> 1][(nf & 1) * 2]);
    };

    const int barid = wc + 1;          // named barriers 1..4, 64 threads each

    for (int s = 0; s < 32; ++s) {
        const int nc = s >> 2, kcb = s & 3;

        // leader: its cp.async group for step s completed (<=1 newer pending);
        // pair barrier publishes readiness to the partner warp AND tells the
        // leader that both warps finished reading buf[(s-1)%3].
        if (leader) { CP_WAIT1; }
        PAIR_BAR(barid);

        // leader refills buf[(s+2)%3] = buf[(s-1)%3] (released by the barrier)
        if (leader && s + 2 < 32) { load_step(s + 2); CP_COMMIT; }

        const uint32_t buf = slice + (uint32_t)(s % 3) * 4096u;

        // software-pipelined fragments: LDSM(k16+1) before MMA(k16)
        uint32_t afX[2][4], bfX[2][4], afY[2][4], bfY[2][4];
        ld_frags(buf, kcb, 0, afX, bfX);
        ld_frags(buf, kcb, 1, afY, bfY);
        do_mmas(afX, bfX);
        ld_frags(buf, kcb, 2, afX, bfX);
        do_mmas(afY, bfY);
        ld_frags(buf, kcb, 3, afY, bfY);
        do_mmas(afX, bfX);
        do_mmas(afY, bfY);

        // ---- epilogue once per 128-col chunk (warp-local) ----
        if (kcb == 3) {
#pragma unroll
            for (int mf = 0; mf < 2; ++mf)
#pragma unroll
                for (int rh = 0; rh < 2; ++rh) {
                    const int row = wr * 32 + mf * 16 + rh * 8 + (l >> 2);
                    const float a2v = a2s[row];
                    float rsum = 0.f;
                    float2 st[4];
#pragma unroll
                    for (int nf = 0; nf < 4; ++nf) {
                        const int mcol = nc * 128 + wc * 32 + nf * 8 + (l & 3) * 2;
                        float d0 = a2v + b2s[mcol]     - 2.f * acc[mf][nf][rh * 2];
                        float d1 = a2v + b2s[mcol + 1] - 2.f * acc[mf][nf][rh * 2 + 1];
                        d0 = fmaxf(d0, 0.f); d1 = fmaxf(d1, 0.f);
                        float q0 = pow_m55(fmaf(d0, 0.1f, 1.f));
                        float q1 = pow_m55(fmaf(d1, 0.1f, 1.f));
                        rsum += q0 + q1;
                        st[nf] = make_float2(q0, q1);
                        acc[mf][nf][rh * 2] = 0.f;
                        acc[mf][nf][rh * 2 + 1] = 0.f;
                    }
                    rsumr[mf][rh] += rsum;
                    float* orow = out + (size_t)(row0 + row) * M_SZ + nc * 128 + wc * 32;
#pragma unroll
                    for (int nf = 0; nf < 4; ++nf)
                        *(float2*)(orow + nf * 8 + (l & 3) * 2) = st[nf];
                }
        }
    }

    // ---- deferred row-sum reduction (once per kernel) ----
#pragma unroll
    for (int mf = 0; mf < 2; ++mf)
#pragma unroll
        for (int rh = 0; rh < 2; ++rh) {
            float v = rsumr[mf][rh];
            v += __shfl_xor_sync(0xffffffffu, v, 1);
            v += __shfl_xor_sync(0xffffffffu, v, 2);
            if ((l & 3) == 0) {
                const int row = wr * 32 + mf * 16 + rh * 8 + (l >> 2);
                atomicAdd(&rss[row], v);
            }
        }

    // ---- fused normalization: re-read tile (L2-resident), scale, rewrite ----
    __syncthreads();
    if (tid < ROWS_CTA) rss[tid] = 1.f / (rss[tid] + 1e-8f);
    __syncthreads();
#pragma unroll 4
    for (int i = tid; i < ROWS_CTA * 256; i += NTHREADS) {
        const int r_ = i >> 8;
        const float inv = rss[r_];
        float4* p4 = reinterpret_cast<float4*>(out + (size_t)(row0 + r_) * M_SZ) + (i & 255);
        float4 v = *p4;
        v.x *= inv; v.y *= inv; v.z *= inv; v.w *= inv;
        *p4 = v;
    }
}

// ---------------------------------------------------------------------------
extern "C" void kernel_launch(void* const* d_in, const int* in_sizes, int n_in,
                              void* d_out, int out_size)
{
    const float* z    = (const float*)d_in[0];   // (16, 3500, 256)
    const float* cent = (const float*)d_in[1];   // (1024, 256)
    const float* tw   = (const float*)d_in[2];   // (3500)
    float* out = (float*)d_out;                  // (16, 3500, 1024)

    cudaFuncSetAttribute(som_mma_kernel,
                         cudaFuncAttributeMaxDynamicSharedMemorySize, SMEM_TOTAL);

    som_prep_kernel<<<M_SZ / 8, 256>>>(cent);
    som_mma_kernel<<<NCTA, NTHREADS, SMEM_TOTAL>>>(z, tw, out);
}